// round 5
// baseline (speedup 1.0000x reference)
#include <cuda_runtime.h>
#include <cstdint>

#define THREADS 1024
#define NWARPS 32
#define RANK 8
#define K4 1024            // K/4
#define N4 1024            // N/4
#define MAXROWS 64
#define RB 2               // rows per phase-1 batch
#define LORA_SCALE 2.0f    // alpha/r = 16/8

// ---- packed f32x2 helpers (FFMA2 only reachable via PTX) ----
__device__ __forceinline__ uint64_t pack2(float lo, float hi) {
    uint64_t r; asm("mov.b64 %0, {%1, %2};" : "=l"(r) : "f"(lo), "f"(hi)); return r;
}
__device__ __forceinline__ void unpack2(uint64_t v, float& lo, float& hi) {
    asm("mov.b64 {%0, %1}, %2;" : "=f"(lo), "=f"(hi) : "l"(v));
}
__device__ __forceinline__ uint64_t fma2(uint64_t a, uint64_t b, uint64_t c) {
    uint64_t d; asm("fma.rn.f32x2 %0, %1, %2, %3;" : "=l"(d) : "l"(a), "l"(b), "l"(c)); return d;
}

__global__ __launch_bounds__(THREADS, 1)
void lora_fused_kernel(const float4* __restrict__ x4,
                       const float4* __restrict__ A4,
                       const float4* __restrict__ B4,
                       float4* __restrict__ out4,
                       int rows, int grid)
{
    extern __shared__ float smem[];
    float* s_part = smem;                      // [MAXROWS][NWARPS][8]  (64 KB)
    float* s_t    = smem + MAXROWS * NWARPS * 8;   // [MAXROWS][8]

    const int tid  = threadIdx.x;
    const int lane = tid & 31;
    const int warp = tid >> 5;

    const int r0 = (int)((long)blockIdx.x * rows / grid);
    const int r1 = (int)((long)(blockIdx.x + 1) * rows / grid);
    const int nr = r1 - r0;                    // <= MAXROWS

    // ---------------- A cache: ONE chunk = 4 k x 4 j-pairs (32 regs) ---------
    uint64_t a2[4][4];
#pragma unroll
    for (int kk = 0; kk < 4; kk++) {
        float4 lo = A4[tid * 8 + kk * 2];      // A[4*tid+kk][0..3]
        float4 hi = A4[tid * 8 + kk * 2 + 1];  // A[4*tid+kk][4..7]
        a2[kk][0] = pack2(lo.x, lo.y);
        a2[kk][1] = pack2(lo.z, lo.w);
        a2[kk][2] = pack2(hi.x, hi.y);
        a2[kk][3] = pack2(hi.z, hi.w);
    }

    const int j_mine = ((lane >> 4) & 1) * 4 + ((lane >> 3) & 1) * 2 + ((lane >> 2) & 1);
    const bool write_lane = (lane & 3) == 0;
    const bool h  = (lane & 16) != 0;
    const bool qb = (lane & 8) != 0;
    const bool ob = (lane & 4) != 0;

    // ---------------- Phase 1: t = x@A, RB rows per batch ---------------------
    for (int rb = 0; rb < nr; rb += RB) {
        float4 xv[RB];
#pragma unroll
        for (int r = 0; r < RB; r++) {         // back-to-back coalesced LDG.128
            int row = rb + r; row = (row < nr) ? row : (nr - 1);
            xv[r] = x4[(size_t)(r0 + row) * K4 + tid];
        }

        uint64_t p2[RB][4];
#pragma unroll
        for (int r = 0; r < RB; r++) {
            const float xc[4] = {xv[r].x, xv[r].y, xv[r].z, xv[r].w};
#pragma unroll
            for (int jp = 0; jp < 4; jp++) p2[r][jp] = 0ull;
#pragma unroll
            for (int kk = 0; kk < 4; kk++) {
                uint64_t xs = pack2(xc[kk], xc[kk]);
#pragma unroll
                for (int jp = 0; jp < 4; jp++)
                    p2[r][jp] = fma2(xs, a2[kk][jp], p2[r][jp]);
            }
        }

        // Folding butterfly reduce (9 shfl per row), rows interleaved
#pragma unroll
        for (int r = 0; r < RB; r++) {
            float p[8];
#pragma unroll
            for (int jp = 0; jp < 4; jp++) unpack2(p2[r][jp], p[2 * jp], p[2 * jp + 1]);

            float q[4];
#pragma unroll
            for (int m = 0; m < 4; m++) {
                float send = h ? p[m] : p[m + 4];
                float keep = h ? p[m + 4] : p[m];
                q[m] = keep + __shfl_xor_sync(0xffffffffu, send, 16);
            }
            float u[2];
#pragma unroll
            for (int m = 0; m < 2; m++) {
                float send = qb ? q[m] : q[m + 2];
                float keep = qb ? q[m + 2] : q[m];
                u[m] = keep + __shfl_xor_sync(0xffffffffu, send, 8);
            }
            float send = ob ? u[0] : u[1];
            float keep = ob ? u[1] : u[0];
            float w = keep + __shfl_xor_sync(0xffffffffu, send, 4);
            w += __shfl_xor_sync(0xffffffffu, w, 2);
            w += __shfl_xor_sync(0xffffffffu, w, 1);
            if (write_lane && (rb + r) < nr)
                s_part[(rb + r) * (NWARPS * 8) + warp * 8 + j_mine] = w;
        }
    }
    __syncthreads();

    // ---------------- Cross-warp reduce into s_t ------------------------------
    for (int i = tid; i < nr * RANK; i += THREADS) {
        const int row = i >> 3, j = i & 7;
        float s = 0.0f;
#pragma unroll
        for (int w = 0; w < NWARPS; w++) s += s_part[row * (NWARPS * 8) + w * 8 + j];
        s_t[i] = s;
    }
    __syncthreads();

    // ---------------- B cache: ONE chunk, 8 j x 2 n-pairs, pre-scaled ---------
    uint64_t b2[8][2];
#pragma unroll
    for (int j = 0; j < RANK; j++) {
        float4 v = B4[j * N4 + tid];
        v.x *= LORA_SCALE; v.y *= LORA_SCALE; v.z *= LORA_SCALE; v.w *= LORA_SCALE;
        b2[j][0] = pack2(v.x, v.y);
        b2[j][1] = pack2(v.z, v.w);
    }

    // ---------------- Phase 2: out = t @ (B*scale) ----------------------------
    for (int r = 0; r < nr; r++) {
        const float4 t0 = *reinterpret_cast<const float4*>(&s_t[r * RANK]);      // broadcast LDS
        const float4 t1 = *reinterpret_cast<const float4*>(&s_t[r * RANK + 4]);

        uint64_t o0 = 0ull, o1 = 0ull;
        o0 = fma2(pack2(t0.x, t0.x), b2[0][0], o0); o1 = fma2(pack2(t0.x, t0.x), b2[0][1], o1);
        o0 = fma2(pack2(t0.y, t0.y), b2[1][0], o0); o1 = fma2(pack2(t0.y, t0.y), b2[1][1], o1);
        o0 = fma2(pack2(t0.z, t0.z), b2[2][0], o0); o1 = fma2(pack2(t0.z, t0.z), b2[2][1], o1);
        o0 = fma2(pack2(t0.w, t0.w), b2[3][0], o0); o1 = fma2(pack2(t0.w, t0.w), b2[3][1], o1);
        o0 = fma2(pack2(t1.x, t1.x), b2[4][0], o0); o1 = fma2(pack2(t1.x, t1.x), b2[4][1], o1);
        o0 = fma2(pack2(t1.y, t1.y), b2[5][0], o0); o1 = fma2(pack2(t1.y, t1.y), b2[5][1], o1);
        o0 = fma2(pack2(t1.z, t1.z), b2[6][0], o0); o1 = fma2(pack2(t1.z, t1.z), b2[6][1], o1);
        o0 = fma2(pack2(t1.w, t1.w), b2[7][0], o0); o1 = fma2(pack2(t1.w, t1.w), b2[7][1], o1);

        float4 o;
        unpack2(o0, o.x, o.y);
        unpack2(o1, o.z, o.w);
        out4[(size_t)(r0 + r) * N4 + tid] = o;     // coalesced STG.128
    }
}

extern "C" void kernel_launch(void* const* d_in, const int* in_sizes, int n_in,
                              void* d_out, int out_size)
{
    const float4* x4 = (const float4*)d_in[0];   // [4,2048,4096]
    const float4* A4 = (const float4*)d_in[1];   // [4096,8]
    const float4* B4 = (const float4*)d_in[2];   // [8,4096]
    float4* out4 = (float4*)d_out;

    const int K    = in_sizes[1] / RANK;         // 4096
    const int rows = in_sizes[0] / K;            // 8192

    int sms = 148;
    cudaDeviceGetAttribute(&sms, cudaDevAttrMultiProcessorCount, 0);

    const int smem = (MAXROWS * NWARPS * 8 + MAXROWS * RANK) * (int)sizeof(float); // ~67.5 KB
    cudaFuncSetAttribute(lora_fused_kernel,
                         cudaFuncAttributeMaxDynamicSharedMemorySize, smem);

    lora_fused_kernel<<<sms, THREADS, smem>>>(x4, A4, B4, out4, rows, sms);
}

// round 6
// speedup vs baseline: 1.1144x; 1.1144x over previous
#include <cuda_runtime.h>
#include <cstdint>

#define THREADS 512
#define NWARPS 16
#define RANK 8
#define K4 1024            // K/4
#define N4 1024            // N/4
#define MAXROWS 64
#define SLOTS 8            // smem ring slots (16KB each)
#define DEPTH 7            // pipeline depth (< SLOTS: refill slot != consume slot)
#define LORA_SCALE 2.0f    // alpha/r = 16/8

// ---- packed f32x2 helpers (FFMA2 only reachable via PTX) ----
__device__ __forceinline__ uint64_t pack2(float lo, float hi) {
    uint64_t r; asm("mov.b64 %0, {%1, %2};" : "=l"(r) : "f"(lo), "f"(hi)); return r;
}
__device__ __forceinline__ void unpack2(uint64_t v, float& lo, float& hi) {
    asm("mov.b64 {%0, %1}, %2;" : "=f"(lo), "=f"(hi) : "l"(v));
}
__device__ __forceinline__ uint64_t fma2(uint64_t a, uint64_t b, uint64_t c) {
    uint64_t d; asm("fma.rn.f32x2 %0, %1, %2, %3;" : "=l"(d) : "l"(a), "l"(b), "l"(c)); return d;
}

// ---- cp.async (LDGSTS) helpers ----
__device__ __forceinline__ void cp_async16(uint32_t dst_smem, const void* src) {
    asm volatile("cp.async.cg.shared.global [%0], [%1], 16;"
                 :: "r"(dst_smem), "l"(src) : "memory");
}
__device__ __forceinline__ void cp_commit() {
    asm volatile("cp.async.commit_group;" ::: "memory");
}
template <int N>
__device__ __forceinline__ void cp_wait() {
    asm volatile("cp.async.wait_group %0;" :: "n"(N) : "memory");
}

__global__ __launch_bounds__(THREADS, 1)
void lora_fused_kernel(const float4* __restrict__ x4,
                       const float4* __restrict__ A4,
                       const float4* __restrict__ B4,
                       float4* __restrict__ out4,
                       int rows, int grid)
{
    extern __shared__ char raw[];
    float4* s_x   = reinterpret_cast<float4*>(raw);               // [SLOTS][1024] (128 KB)
    float*  s_part = reinterpret_cast<float*>(raw + SLOTS * K4 * 16); // [MAXROWS][NWARPS][8] (32 KB)
    float*  s_t    = s_part + MAXROWS * NWARPS * 8;               // [MAXROWS][8]

    const int tid  = threadIdx.x;
    const int lane = tid & 31;
    const int warp = tid >> 5;

    const int r0 = (int)((long)blockIdx.x * rows / grid);
    const int r1 = (int)((long)(blockIdx.x + 1) * rows / grid);
    const int nr = r1 - r0;                    // ~54, > DEPTH

    const int c0 = tid;
    const int c1 = tid + THREADS;

    const uint32_t sx = (uint32_t)__cvta_generic_to_shared(s_x);
    const uint32_t my_off = (uint32_t)tid * 16u;

    // ---------------- A cache: 2 chunks x 4 k x 4 j-pairs (64 regs) ----------
    uint64_t a2[2][4][4];
#pragma unroll
    for (int ch = 0; ch < 2; ch++) {
        const int c = ch ? c1 : c0;
#pragma unroll
        for (int kk = 0; kk < 4; kk++) {
            float4 lo = A4[c * 8 + kk * 2];
            float4 hi = A4[c * 8 + kk * 2 + 1];
            a2[ch][kk][0] = pack2(lo.x, lo.y);
            a2[ch][kk][1] = pack2(lo.z, lo.w);
            a2[ch][kk][2] = pack2(hi.x, hi.y);
            a2[ch][kk][3] = pack2(hi.z, hi.w);
        }
    }

    const int j_mine = ((lane >> 4) & 1) * 4 + ((lane >> 3) & 1) * 2 + ((lane >> 2) & 1);
    const bool write_lane = (lane & 3) == 0;
    const bool h  = (lane & 16) != 0;
    const bool qb = (lane & 8) != 0;
    const bool ob = (lane & 4) != 0;

    // ---------------- Prologue: stage first DEPTH rows into the ring ---------
#pragma unroll
    for (int d = 0; d < DEPTH; d++) {
        int row = (d < nr) ? d : (nr - 1);
        const size_t xb = (size_t)(r0 + row) * K4;
        uint32_t dst = sx + (uint32_t)(d & (SLOTS - 1)) * (K4 * 16u) + my_off;
        cp_async16(dst,                    x4 + xb + c0);
        cp_async16(dst + THREADS * 16u,    x4 + xb + c1);
        cp_commit();
    }

    // ---------------- Phase 1: barrier-free pipelined t = x@A -----------------
    for (int rb = 0; rb < nr; rb++) {
        cp_wait<DEPTH - 1>();              // row rb complete (per-thread data)

        const int slot = rb & (SLOTS - 1);
        const float4 xa = s_x[slot * K4 + c0];   // LDS.128, thread-private
        const float4 xb = s_x[slot * K4 + c1];

        uint64_t p2[4] = {0ull, 0ull, 0ull, 0ull};
        {
            const float xc[4] = {xa.x, xa.y, xa.z, xa.w};
#pragma unroll
            for (int kk = 0; kk < 4; kk++) {
                uint64_t xs = pack2(xc[kk], xc[kk]);
#pragma unroll
                for (int jp = 0; jp < 4; jp++)
                    p2[jp] = fma2(xs, a2[0][kk][jp], p2[jp]);
            }
        }
        {
            const float xc[4] = {xb.x, xb.y, xb.z, xb.w};
#pragma unroll
            for (int kk = 0; kk < 4; kk++) {
                uint64_t xs = pack2(xc[kk], xc[kk]);
#pragma unroll
                for (int jp = 0; jp < 4; jp++)
                    p2[jp] = fma2(xs, a2[1][kk][jp], p2[jp]);
            }
        }

        // Refill row rb+DEPTH into slot (rb+DEPTH)&7 (!= current slot)
        const int rr = rb + DEPTH;
        if (rr < nr) {
            const size_t xbs = (size_t)(r0 + rr) * K4;
            uint32_t dst = sx + (uint32_t)(rr & (SLOTS - 1)) * (K4 * 16u) + my_off;
            cp_async16(dst,                 x4 + xbs + c0);
            cp_async16(dst + THREADS * 16u, x4 + xbs + c1);
        }
        cp_commit();                        // empty group in the tail keeps invariant

        // Folding butterfly reduce (9 SHFL)
        float p[8];
#pragma unroll
        for (int jp = 0; jp < 4; jp++) unpack2(p2[jp], p[2 * jp], p[2 * jp + 1]);

        float q[4];
#pragma unroll
        for (int m = 0; m < 4; m++) {
            float send = h ? p[m] : p[m + 4];
            float keep = h ? p[m + 4] : p[m];
            q[m] = keep + __shfl_xor_sync(0xffffffffu, send, 16);
        }
        float u[2];
#pragma unroll
        for (int m = 0; m < 2; m++) {
            float send = qb ? q[m] : q[m + 2];
            float keep = qb ? q[m + 2] : q[m];
            u[m] = keep + __shfl_xor_sync(0xffffffffu, send, 8);
        }
        float send = ob ? u[0] : u[1];
        float keep = ob ? u[1] : u[0];
        float w = keep + __shfl_xor_sync(0xffffffffu, send, 4);
        w += __shfl_xor_sync(0xffffffffu, w, 2);
        w += __shfl_xor_sync(0xffffffffu, w, 1);
        if (write_lane)
            s_part[rb * (NWARPS * 8) + warp * 8 + j_mine] = w;
    }

    // ---------------- B cache (overlaps with other warps finishing) ----------
    uint64_t b2[2][8][2];
#pragma unroll
    for (int ch = 0; ch < 2; ch++) {
        const int c = ch ? c1 : c0;
#pragma unroll
        for (int j = 0; j < RANK; j++) {
            float4 v = B4[j * N4 + c];
            v.x *= LORA_SCALE; v.y *= LORA_SCALE; v.z *= LORA_SCALE; v.w *= LORA_SCALE;
            b2[ch][j][0] = pack2(v.x, v.y);
            b2[ch][j][1] = pack2(v.z, v.w);
        }
    }

    __syncthreads();

    // ---------------- Cross-warp reduce into s_t ------------------------------
    for (int i = tid; i < nr * RANK; i += THREADS) {
        const int row = i >> 3, j = i & 7;
        float s = 0.0f;
#pragma unroll
        for (int w16 = 0; w16 < NWARPS; w16++)
            s += s_part[row * (NWARPS * 8) + w16 * 8 + j];
        s_t[i] = s;
    }
    __syncthreads();

    // ---------------- Phase 2: out = t @ (B*scale), 2 rows/iter ---------------
    for (int rb = 0; rb < nr; rb += 2) {
        const int rA = rb;
        const int rB = (rb + 1 < nr) ? rb + 1 : rb;   // clamp (dup store harmless)

        float4 tA0 = *reinterpret_cast<const float4*>(&s_t[rA * RANK]);
        float4 tA1 = *reinterpret_cast<const float4*>(&s_t[rA * RANK + 4]);
        float4 tB0 = *reinterpret_cast<const float4*>(&s_t[rB * RANK]);
        float4 tB1 = *reinterpret_cast<const float4*>(&s_t[rB * RANK + 4]);

        uint64_t tsA[8], tsB[8];
        tsA[0] = pack2(tA0.x, tA0.x); tsA[1] = pack2(tA0.y, tA0.y);
        tsA[2] = pack2(tA0.z, tA0.z); tsA[3] = pack2(tA0.w, tA0.w);
        tsA[4] = pack2(tA1.x, tA1.x); tsA[5] = pack2(tA1.y, tA1.y);
        tsA[6] = pack2(tA1.z, tA1.z); tsA[7] = pack2(tA1.w, tA1.w);
        tsB[0] = pack2(tB0.x, tB0.x); tsB[1] = pack2(tB0.y, tB0.y);
        tsB[2] = pack2(tB0.z, tB0.z); tsB[3] = pack2(tB0.w, tB0.w);
        tsB[4] = pack2(tB1.x, tB1.x); tsB[5] = pack2(tB1.y, tB1.y);
        tsB[6] = pack2(tB1.z, tB1.z); tsB[7] = pack2(tB1.w, tB1.w);

        const size_t obA = (size_t)(r0 + rA) * N4;
        const size_t obB = (size_t)(r0 + rB) * N4;
#pragma unroll
        for (int ch = 0; ch < 2; ch++) {
            const int c = ch ? c1 : c0;
            uint64_t oA0 = 0ull, oA1 = 0ull, oB0 = 0ull, oB1 = 0ull;
#pragma unroll
            for (int j = 0; j < RANK; j++) {
                oA0 = fma2(tsA[j], b2[ch][j][0], oA0);
                oA1 = fma2(tsA[j], b2[ch][j][1], oA1);
                oB0 = fma2(tsB[j], b2[ch][j][0], oB0);
                oB1 = fma2(tsB[j], b2[ch][j][1], oB1);
            }
            float4 oA, oB;
            unpack2(oA0, oA.x, oA.y); unpack2(oA1, oA.z, oA.w);
            unpack2(oB0, oB.x, oB.y); unpack2(oB1, oB.z, oB.w);
            out4[obA + c] = oA;
            out4[obB + c] = oB;
        }
    }
}

extern "C" void kernel_launch(void* const* d_in, const int* in_sizes, int n_in,
                              void* d_out, int out_size)
{
    const float4* x4 = (const float4*)d_in[0];   // [4,2048,4096]
    const float4* A4 = (const float4*)d_in[1];   // [4096,8]
    const float4* B4 = (const float4*)d_in[2];   // [8,4096]
    float4* out4 = (float4*)d_out;

    const int K    = in_sizes[1] / RANK;         // 4096
    const int rows = in_sizes[0] / K;            // 8192

    int sms = 148;
    cudaDeviceGetAttribute(&sms, cudaDevAttrMultiProcessorCount, 0);

    const int smem = SLOTS * K4 * 16 +                         // x ring: 128 KB
                     MAXROWS * NWARPS * 8 * (int)sizeof(float) + // partials: 32 KB
                     MAXROWS * RANK * (int)sizeof(float);        // t: 2 KB
    cudaFuncSetAttribute(lora_fused_kernel,
                         cudaFuncAttributeMaxDynamicSharedMemorySize, smem);

    lora_fused_kernel<<<sms, THREADS, smem>>>(x4, A4, B4, out4, rows, sms);
}